// round 6
// baseline (speedup 1.0000x reference)
#include <cuda_runtime.h>
#include <cstdint>
#include <math.h>

// AFMADEBlock: incremental triangular evaluation of the MADE autoregressive
// inverse. One degree-group finalized per step (31 steps).
//
// R6: occupancy reshape. RPW=2 (accumulators 64 regs -> 128 regs/thread),
// NWARP=7 / 14 rows per block / grid 296 = 2x148 -> exactly 2 blocks on
// every SM (no idle SMs), 14 warps/SM for latency hiding (R5: 8 warps,
// issue=44%). Layer-1/2 h reads vectorized to LDS.128 ({h,h,h,h} row
// pairs) halving h-broadcast traffic. Keeps: dead-block skip (4 (CNT,E0)
// variants), fma.rn.f32x2, cp.async double-buffered weight staging.

#define Dd 32
#define Bb 4096
#define EPSf 1e-12f
#define RPW 2                  // rows per warp
#define NWARP 7                // warps per block
#define THREADS (NWARP * 32)   // 224
#define ROWS_PER_BLOCK (NWARP * RPW)   // 14
#define GRID 296               // 2 blocks per SM on 148 SMs; 296*14=4144 rows (48 padded)

// Permuted+masked weights (hidden units sorted by degree). ~656KB, static.
__device__ __align__(16) float g_W0p[2][32][256];
__device__ __align__(16) float g_W1p[2][256][256];
__device__ __align__(16) float g_W2p[2][256][32];
__device__ __align__(16) float g_b0p[2][256];
__device__ __align__(16) float g_b1p[2][256];
__device__ __align__(16) float g_b2[2][32];

// deg(i) = (i % 31) + 1 for original hidden index i.
// Sorted order: degrees 1..8 have 9 units, degrees 9..31 have 8 units.
__device__ __forceinline__ int degS(int k) {
    return (k < 72) ? (k / 9 + 1) : ((k - 72) / 8 + 9);
}
__device__ __forceinline__ int permS(int k) {
    int d, jj;
    if (k < 72) { d = k / 9 + 1;        jj = k % 9; }
    else        { d = (k - 72) / 8 + 9; jj = (k - 72) % 8; }
    return (d - 1) + 31 * jj;   // original index of k-th sorted unit
}

__global__ void prep_kernel(
    const float* __restrict__ mu_W0, const float* __restrict__ mu_b0,
    const float* __restrict__ mu_W1, const float* __restrict__ mu_b1,
    const float* __restrict__ mu_W2, const float* __restrict__ mu_b2,
    const float* __restrict__ lv_W0, const float* __restrict__ lv_b0,
    const float* __restrict__ lv_W1, const float* __restrict__ lv_b1,
    const float* __restrict__ lv_W2, const float* __restrict__ lv_b2)
{
    int idx = blockIdx.x * blockDim.x + threadIdx.x;
    if (idx >= 2 * 256 * 256) return;
    int net = idx >> 16;
    int k   = (idx >> 8) & 255;   // sorted hidden row
    int c   = idx & 255;          // sorted hidden col

    const float* W0 = net ? lv_W0 : mu_W0;
    const float* b0 = net ? lv_b0 : mu_b0;
    const float* W1 = net ? lv_W1 : mu_W1;
    const float* b1 = net ? lv_b1 : mu_b1;
    const float* W2 = net ? lv_W2 : mu_W2;
    const float* b2 = net ? lv_b2 : mu_b2;

    int dk = degS(k), pk = permS(k);
    int dc = degS(c), pc = permS(c);

    g_W1p[net][k][c] = (dc >= dk) ? W1[pk * 256 + pc] : 0.f;
    if (k < 32) g_W0p[net][k][c] = (dc >= (k + 1)) ? W0[k * 256 + pc] : 0.f;
    if (c < 32) g_W2p[net][k][c] = ((c + 1) > dk) ? W2[pk * 32 + c] : 0.f;
    if (k == 0) {
        g_b0p[net][c] = b0[pc];
        g_b1p[net][c] = b1[pc];
        if (c < 32) g_b2[net][c] = b2[c];
    }
}

__device__ __forceinline__ void cp16(void* s, const void* g) {
    unsigned int sa = (unsigned int)__cvta_generic_to_shared(s);
    asm volatile("cp.async.cg.shared.global [%0], [%1], 16;" :: "r"(sa), "l"(g));
}
__device__ __forceinline__ void cp_commit() {
    asm volatile("cp.async.commit_group;");
}
__device__ __forceinline__ void cp_wait_all() {
    asm volatile("cp.async.wait_group 0;");
}

// Packed dual-fp32 FMA: d = a*b + d (elementwise on the two f32 halves).
__device__ __forceinline__ void ffma2(float2& d, const float2& a, const float2& b) {
    asm("fma.rn.f32x2 %0, %1, %2, %0;"
        : "+l"(reinterpret_cast<unsigned long long&>(d))
        : "l"(reinterpret_cast<const unsigned long long&>(a)),
          "l"(reinterpret_cast<const unsigned long long&>(b)));
}

// One degree-group step. Lane l owns cols 64e+2l+{0,1}, e in [E0,4).
// CNT = group size, E0 = first alive 64-col block (= off>>6).
template<int CNT, int E0>
__device__ __forceinline__ void do_step(
    int l, int off, int buf, const float2 y2[RPW],
    float2 a0[2][RPW][4], float2 a1[2][RPW][4], float2 aout2[2],
    const float* SW0, const float* SW1, const float* SW2,
    float2 (*sH0)[9][RPW], float2 (*sH1)[9])
{
    // ---- layer 0: a0 += y_j * W0row ----
#pragma unroll
    for (int net = 0; net < 2; net++) {
#pragma unroll
        for (int e = E0; e < 4; e++) {
            float2 wv = *(const float2*)(SW0 + (buf * 2 + net) * 256 + 64 * e + 2 * l);
#pragma unroll
            for (int r = 0; r < RPW; r++) ffma2(a0[net][r][e], wv, y2[r]);
        }
    }
    // finalize h0 group [off, off+CNT) -> sH0[net][u][r] = {h,h}
#pragma unroll
    for (int net = 0; net < 2; net++) {
#pragma unroll
        for (int e = E0; e < 4; e++) {
            int u0 = 64 * e + 2 * l - off;
            if (u0 >= 0 && u0 < CNT) {
#pragma unroll
                for (int r = 0; r < RPW; r++) {
                    float h = fmaxf(a0[net][r][e].x, 0.f);
                    sH0[net][u0][r] = make_float2(h, h);
                }
            }
            if (u0 + 1 >= 0 && u0 + 1 < CNT) {
#pragma unroll
                for (int r = 0; r < RPW; r++) {
                    float h = fmaxf(a0[net][r][e].y, 0.f);
                    sH0[net][u0 + 1][r] = make_float2(h, h);
                }
            }
        }
    }
    __syncwarp();

    // ---- layer 1: a1 += h0_group @ W1 rows (h via one LDS.128 per (net,u)) ----
#pragma unroll
    for (int net = 0; net < 2; net++) {
#pragma unroll
        for (int u = 0; u < CNT; u++) {
            const float* wr = SW1 + ((buf * 2 + net) * 9 + u) * 256;
            float2 wv[4];
#pragma unroll
            for (int e = E0; e < 4; e++)
                wv[e] = *(const float2*)(wr + 64 * e + 2 * l);
            float4 hh = *(const float4*)&sH0[net][u][0];   // {h0,h0,h1,h1}
            float2 h0 = make_float2(hh.x, hh.y);
            float2 h1 = make_float2(hh.z, hh.w);
#pragma unroll
            for (int e = E0; e < 4; e++) {
                ffma2(a1[net][0][e], wv[e], h0);
                ffma2(a1[net][1][e], wv[e], h1);
            }
        }
    }
    // finalize h1 group -> sH1[net][u] = {h(row0), h(row1)}
#pragma unroll
    for (int net = 0; net < 2; net++) {
#pragma unroll
        for (int e = E0; e < 4; e++) {
            int u0 = 64 * e + 2 * l - off;
            if (u0 >= 0 && u0 < CNT)
                sH1[net][u0] = make_float2(fmaxf(a1[net][0][e].x, 0.f),
                                           fmaxf(a1[net][1][e].x, 0.f));
            if (u0 + 1 >= 0 && u0 + 1 < CNT)
                sH1[net][u0 + 1] = make_float2(fmaxf(a1[net][0][e].y, 0.f),
                                               fmaxf(a1[net][1][e].y, 0.f));
        }
    }
    __syncwarp();

    // ---- layer 2: aout += h1_group @ W2 rows (row-pair packed) ----
#pragma unroll
    for (int net = 0; net < 2; net++) {
#pragma unroll
        for (int u = 0; u < CNT; u++) {
            float wvf = SW2[((buf * 2 + net) * 9 + u) * 32 + l];
            float2 w2 = make_float2(wvf, wvf);
            float2 h2 = sH1[net][u];          // {h_row0, h_row1}
            ffma2(aout2[net], h2, w2);
        }
    }
}

// Prefetch weights for a step (row j, group offset off) into buffer buf.
// Only alive columns [64*E0, 256) are fetched.
template<int CNT, int E0>
__device__ __forceinline__ void prefetch_step(
    int j, int off, int tid, int buf,
    float* SW0, float* SW1, float* SW2)
{
    constexpr int KC = 64 - 16 * E0;   // 16B chunks per W0/W1 row
#pragma unroll
    for (int net = 0; net < 2; net++) {
        if (tid < KC)
            cp16(SW0 + (buf * 2 + net) * 256 + 64 * E0 + 4 * tid,
                 &g_W0p[net][j][64 * E0 + 4 * tid]);
        for (int i = tid; i < CNT * KC; i += THREADS) {
            int u = i / KC, q = i % KC;
            cp16(SW1 + ((buf * 2 + net) * 9 + u) * 256 + 64 * E0 + 4 * q,
                 &g_W1p[net][off + u][64 * E0 + 4 * q]);
        }
        for (int i = tid; i < CNT * 8; i += THREADS) {
            int u = i >> 3, q = i & 7;
            cp16(SW2 + ((buf * 2 + net) * 9 + u) * 32 + 4 * q,
                 &g_W2p[net][off + u][4 * q]);
        }
    }
}

__global__ __launch_bounds__(THREADS, 2)
void afmade_kernel(const float* __restrict__ x, float* __restrict__ out)
{
    // dynamic smem: SW0 [2buf][2net][256] | SW1 [2][2][9][256] | SW2 [2][2][9][32]
    extern __shared__ __align__(16) unsigned char dynsm[];
    float* SW0 = (float*)dynsm;          // 1024 floats
    float* SW1 = SW0 + 1024;             // 9216 floats
    float* SW2 = SW1 + 9216;             // 1152 floats

    __shared__ __align__(16) float2 sH0s[NWARP][2][9][RPW];
    __shared__ __align__(16) float2 sH1s[NWARP][2][9];

    const int tid = threadIdx.x;
    const int w   = tid >> 5;
    const int l   = tid & 31;
    const int base_row = blockIdx.x * ROWS_PER_BLOCK + w * RPW;

    float2 a0[2][RPW][4], a1[2][RPW][4], aout2[2];
    float  lssum[RPW], xr[RPW];

#pragma unroll
    for (int net = 0; net < 2; net++) {
#pragma unroll
        for (int e = 0; e < 4; e++) {
            float2 b0v = *(const float2*)&g_b0p[net][64 * e + 2 * l];
            float2 b1v = *(const float2*)&g_b1p[net][64 * e + 2 * l];
#pragma unroll
            for (int r = 0; r < RPW; r++) { a0[net][r][e] = b0v; a1[net][r][e] = b1v; }
        }
        float b2v = g_b2[net][l];
        aout2[net] = make_float2(b2v, b2v);
    }
#pragma unroll
    for (int r = 0; r < RPW; r++) {
        lssum[r] = 0.f;
        int row = base_row + r;
        xr[r] = (row < Bb) ? x[row * 32 + l] : 0.f;   // lane l holds x[., l]
    }

    // Prologue: prefetch step 1 into buffer 0.
    prefetch_step<9, 0>(0, 0, tid, 0, SW0, SW1, SW2);
    cp_commit();

    int buf = 0;
    for (int t = 1; t <= 32; ++t) {
        const int j = t - 1;
        // ---- emit coordinate j (registers only; overlaps in-flight prefetch) ----
        float2 y2[RPW];
#pragma unroll
        for (int r = 0; r < RPW; r++) {
            float mu = r ? aout2[0].y : aout2[0].x;
            float lv = r ? aout2[1].y : aout2[1].x;
            float ls = 0.5f * lv;
            float yc = __fdividef(xr[r] - mu, __expf(ls) + EPSf);
            if (l == j) {
                lssum[r] += ls;
                if (base_row + r < Bb) out[(base_row + r) * 32 + j] = yc;
            }
            float yv = __shfl_sync(0xffffffffu, yc, j);
            y2[r] = make_float2(yv, yv);
        }
        if (t == 32) break;

        cp_wait_all();
        __syncthreads();

        if (t < 31) {
            const int tn = t + 1, jn = tn - 1;
            const int offn = (tn <= 9) ? 9 * (tn - 1) : 72 + 8 * (tn - 9);
            if (tn <= 8)       prefetch_step<9, 0>(jn, offn, tid, buf ^ 1, SW0, SW1, SW2);
            else if (tn <= 15) prefetch_step<8, 1>(jn, offn, tid, buf ^ 1, SW0, SW1, SW2);
            else if (tn <= 23) prefetch_step<8, 2>(jn, offn, tid, buf ^ 1, SW0, SW1, SW2);
            else               prefetch_step<8, 3>(jn, offn, tid, buf ^ 1, SW0, SW1, SW2);
            cp_commit();
        }

        const int off = (t <= 9) ? 9 * (t - 1) : 72 + 8 * (t - 9);
        if (t <= 8)
            do_step<9, 0>(l, off, buf, y2, a0, a1, aout2, SW0, SW1, SW2, sH0s[w], sH1s[w]);
        else if (t <= 15)
            do_step<8, 1>(l, off, buf, y2, a0, a1, aout2, SW0, SW1, SW2, sH0s[w], sH1s[w]);
        else if (t <= 23)
            do_step<8, 2>(l, off, buf, y2, a0, a1, aout2, SW0, SW1, SW2, sH0s[w], sH1s[w]);
        else
            do_step<8, 3>(l, off, buf, y2, a0, a1, aout2, SW0, SW1, SW2, sH0s[w], sH1s[w]);
        buf ^= 1;
    }

    // ---- logstd row-sums (lane l holds coordinate l's contribution) ----
#pragma unroll
    for (int r = 0; r < RPW; r++) {
        float s = lssum[r];
#pragma unroll
        for (int o = 16; o > 0; o >>= 1) s += __shfl_xor_sync(0xffffffffu, s, o);
        if (l == 0 && base_row + r < Bb) out[Bb * Dd + base_row + r] = s;
    }
}

extern "C" void kernel_launch(void* const* d_in, const int* in_sizes, int n_in,
                              void* d_out, int out_size)
{
    (void)in_sizes; (void)n_in; (void)out_size;
    const float* x = (const float*)d_in[0];

    prep_kernel<<<512, 256>>>(
        (const float*)d_in[1],  (const float*)d_in[2],  (const float*)d_in[3],
        (const float*)d_in[4],  (const float*)d_in[5],  (const float*)d_in[6],
        (const float*)d_in[7],  (const float*)d_in[8],  (const float*)d_in[9],
        (const float*)d_in[10], (const float*)d_in[11], (const float*)d_in[12]);

    const int dyn_smem = (1024 + 9216 + 1152) * 4;   // 45568 B
    cudaFuncSetAttribute(afmade_kernel,
                         cudaFuncAttributeMaxDynamicSharedMemorySize, dyn_smem);
    afmade_kernel<<<GRID, THREADS, dyn_smem>>>(x, (float*)d_out);
}

// round 7
// speedup vs baseline: 1.1855x; 1.1855x over previous
#include <cuda_runtime.h>
#include <cstdint>
#include <math.h>

// AFMADEBlock: incremental triangular evaluation of the MADE autoregressive
// inverse. One degree-group finalized per step (31 steps).
//
// R7: net-split warp pairs. Warp pair = {mu-warp, lv-warp} over the SAME 8
// rows; each warp loads only its net's weights -> total weight-LDS bytes
// halved vs R5 at the same register budget (R6 showed LDS traffic ~ warp
// count is the binding resource). Cross-net emit exchange rides the existing
// per-step __syncthreads (double-buffered smem), replacing the shfl
// broadcast. Keeps: dead-block skip, fma.rn.f32x2, cp.async double buffer.

#define Dd 32
#define Bb 4096
#define EPSf 1e-12f
#define RPW 8                  // rows per warp pair
#define NPAIR 2                // warp pairs per block
#define NWARP (2 * NPAIR)      // 4 warps
#define THREADS (NWARP * 32)   // 128
#define ROWS_PER_BLOCK (NPAIR * RPW)   // 16
#define GRID (Bb / ROWS_PER_BLOCK)     // 256

// Permuted+masked weights (hidden units sorted by degree). ~656KB, static.
__device__ __align__(16) float g_W0p[2][32][256];
__device__ __align__(16) float g_W1p[2][256][256];
__device__ __align__(16) float g_W2p[2][256][32];
__device__ __align__(16) float g_b0p[2][256];
__device__ __align__(16) float g_b1p[2][256];
__device__ __align__(16) float g_b2[2][32];

// deg(i) = (i % 31) + 1 for original hidden index i.
// Sorted order: degrees 1..8 have 9 units, degrees 9..31 have 8 units.
__device__ __forceinline__ int degS(int k) {
    return (k < 72) ? (k / 9 + 1) : ((k - 72) / 8 + 9);
}
__device__ __forceinline__ int permS(int k) {
    int d, jj;
    if (k < 72) { d = k / 9 + 1;        jj = k % 9; }
    else        { d = (k - 72) / 8 + 9; jj = (k - 72) % 8; }
    return (d - 1) + 31 * jj;   // original index of k-th sorted unit
}

__global__ void prep_kernel(
    const float* __restrict__ mu_W0, const float* __restrict__ mu_b0,
    const float* __restrict__ mu_W1, const float* __restrict__ mu_b1,
    const float* __restrict__ mu_W2, const float* __restrict__ mu_b2,
    const float* __restrict__ lv_W0, const float* __restrict__ lv_b0,
    const float* __restrict__ lv_W1, const float* __restrict__ lv_b1,
    const float* __restrict__ lv_W2, const float* __restrict__ lv_b2)
{
    int idx = blockIdx.x * blockDim.x + threadIdx.x;
    if (idx >= 2 * 256 * 256) return;
    int net = idx >> 16;
    int k   = (idx >> 8) & 255;   // sorted hidden row
    int c   = idx & 255;          // sorted hidden col

    const float* W0 = net ? lv_W0 : mu_W0;
    const float* b0 = net ? lv_b0 : mu_b0;
    const float* W1 = net ? lv_W1 : mu_W1;
    const float* b1 = net ? lv_b1 : mu_b1;
    const float* W2 = net ? lv_W2 : mu_W2;
    const float* b2 = net ? lv_b2 : mu_b2;

    int dk = degS(k), pk = permS(k);
    int dc = degS(c), pc = permS(c);

    g_W1p[net][k][c] = (dc >= dk) ? W1[pk * 256 + pc] : 0.f;
    if (k < 32) g_W0p[net][k][c] = (dc >= (k + 1)) ? W0[k * 256 + pc] : 0.f;
    if (c < 32) g_W2p[net][k][c] = ((c + 1) > dk) ? W2[pk * 32 + c] : 0.f;
    if (k == 0) {
        g_b0p[net][c] = b0[pc];
        g_b1p[net][c] = b1[pc];
        if (c < 32) g_b2[net][c] = b2[c];
    }
}

__device__ __forceinline__ void cp16(void* s, const void* g) {
    unsigned int sa = (unsigned int)__cvta_generic_to_shared(s);
    asm volatile("cp.async.cg.shared.global [%0], [%1], 16;" :: "r"(sa), "l"(g));
}
__device__ __forceinline__ void cp_commit() {
    asm volatile("cp.async.commit_group;");
}
__device__ __forceinline__ void cp_wait_all() {
    asm volatile("cp.async.wait_group 0;");
}

// Packed dual-fp32 FMA: d = a*b + d (elementwise on the two f32 halves).
__device__ __forceinline__ void ffma2(float2& d, const float2& a, const float2& b) {
    asm("fma.rn.f32x2 %0, %1, %2, %0;"
        : "+l"(reinterpret_cast<unsigned long long&>(d))
        : "l"(reinterpret_cast<const unsigned long long&>(a)),
          "l"(reinterpret_cast<const unsigned long long&>(b)));
}

// One degree-group step for ONE net over 8 rows.
// Lane l owns cols 64e+2l+{0,1}, e in [E0,4). CNT = group size, E0 = off>>6.
template<int CNT, int E0>
__device__ __forceinline__ void do_step(
    int l, int off, int buf, int net, const float2 y2[RPW],
    float2 a0[RPW][4], float2 a1[RPW][4], float2 aout2[4],
    const float* SW0, const float* SW1, const float* SW2,
    float2 (*sH0)[RPW], float (*sH1)[RPW])
{
    const float* W0 = SW0 + (buf * 2 + net) * 256;
    // ---- layer 0: a0 += y_j * W0row ----
#pragma unroll
    for (int e = E0; e < 4; e++) {
        float2 wv = *(const float2*)(W0 + 64 * e + 2 * l);
#pragma unroll
        for (int r = 0; r < RPW; r++) ffma2(a0[r][e], wv, y2[r]);
    }
    // finalize h0 group [off, off+CNT): owner lane stores {h,h} per row
#pragma unroll
    for (int e = E0; e < 4; e++) {
        int u0 = 64 * e + 2 * l - off;
        if (u0 >= 0 && u0 < CNT) {
#pragma unroll
            for (int r = 0; r < RPW; r++) {
                float h = fmaxf(a0[r][e].x, 0.f);
                sH0[u0][r] = make_float2(h, h);
            }
        }
        if (u0 + 1 >= 0 && u0 + 1 < CNT) {
#pragma unroll
            for (int r = 0; r < RPW; r++) {
                float h = fmaxf(a0[r][e].y, 0.f);
                sH0[u0 + 1][r] = make_float2(h, h);
            }
        }
    }
    __syncwarp();

    // ---- layer 1: a1 += h0_group @ W1 rows ----
#pragma unroll
    for (int u = 0; u < CNT; u++) {
        const float* wr = SW1 + ((buf * 2 + net) * 9 + u) * 256;
        float2 wv[4];
#pragma unroll
        for (int e = E0; e < 4; e++)
            wv[e] = *(const float2*)(wr + 64 * e + 2 * l);
#pragma unroll
        for (int q = 0; q < RPW / 2; q++) {
            float4 hq = *(const float4*)&sH0[u][2 * q];  // {h,h,h',h'} rows 2q,2q+1
            float2 hA = make_float2(hq.x, hq.y);
            float2 hB = make_float2(hq.z, hq.w);
#pragma unroll
            for (int e = E0; e < 4; e++) {
                ffma2(a1[2 * q][e], wv[e], hA);
                ffma2(a1[2 * q + 1][e], wv[e], hB);
            }
        }
    }
    // finalize h1 group: owner lane stores scalar h per row
#pragma unroll
    for (int e = E0; e < 4; e++) {
        int u0 = 64 * e + 2 * l - off;
        if (u0 >= 0 && u0 < CNT) {
#pragma unroll
            for (int r = 0; r < RPW; r++)
                sH1[u0][r] = fmaxf(a1[r][e].x, 0.f);
        }
        if (u0 + 1 >= 0 && u0 + 1 < CNT) {
#pragma unroll
            for (int r = 0; r < RPW; r++)
                sH1[u0 + 1][r] = fmaxf(a1[r][e].y, 0.f);
        }
    }
    __syncwarp();

    // ---- layer 2: aout += h1_group @ W2 rows (row-pair packed) ----
#pragma unroll
    for (int u = 0; u < CNT; u++) {
        float wf = SW2[((buf * 2 + net) * 9 + u) * 32 + l];
        float2 w2 = make_float2(wf, wf);
        float4 hA = *(const float4*)&sH1[u][0];   // rows 0..3
        float4 hB = *(const float4*)&sH1[u][4];   // rows 4..7
        ffma2(aout2[0], make_float2(hA.x, hA.y), w2);
        ffma2(aout2[1], make_float2(hA.z, hA.w), w2);
        ffma2(aout2[2], make_float2(hB.x, hB.y), w2);
        ffma2(aout2[3], make_float2(hB.z, hB.w), w2);
    }
}

// Prefetch weights for a step (row j, group offset off) into buffer buf.
// Only alive columns [64*E0, 256) are fetched. Both nets staged per block.
template<int CNT, int E0>
__device__ __forceinline__ void prefetch_step(
    int j, int off, int tid, int buf,
    float* SW0, float* SW1, float* SW2)
{
    constexpr int KC = 64 - 16 * E0;   // 16B chunks per W0/W1 row
#pragma unroll
    for (int net = 0; net < 2; net++) {
        if (tid < KC)
            cp16(SW0 + (buf * 2 + net) * 256 + 64 * E0 + 4 * tid,
                 &g_W0p[net][j][64 * E0 + 4 * tid]);
        for (int i = tid; i < CNT * KC; i += THREADS) {
            int u = i / KC, q = i % KC;
            cp16(SW1 + ((buf * 2 + net) * 9 + u) * 256 + 64 * E0 + 4 * q,
                 &g_W1p[net][off + u][64 * E0 + 4 * q]);
        }
        for (int i = tid; i < CNT * 8; i += THREADS) {
            int u = i >> 3, q = i & 7;
            cp16(SW2 + ((buf * 2 + net) * 9 + u) * 32 + 4 * q,
                 &g_W2p[net][off + u][4 * q]);
        }
    }
}

__global__ __launch_bounds__(THREADS, 2)
void afmade_kernel(const float* __restrict__ x, float* __restrict__ out)
{
    // dynamic smem: SW0 [2buf][2net][256] | SW1 [2][2][9][256] | SW2 [2][2][9][32]
    extern __shared__ __align__(16) unsigned char dynsm[];
    float* SW0 = (float*)dynsm;          // 1024 floats
    float* SW1 = SW0 + 1024;             // 9216 floats
    float* SW2 = SW1 + 9216;             // 1152 floats

    __shared__ __align__(16) float2 sH0s[NWARP][9][RPW];  // per-warp h0 {h,h}
    __shared__ __align__(16) float  sH1s[NWARP][9][RPW];  // per-warp h1 scalar
    __shared__ __align__(16) float2 sD[2][NPAIR][4];      // (x - mu) row pairs
    __shared__ __align__(16) float2 sI[2][NPAIR][4];      // 1/(exp(ls)+eps)

    const int tid  = threadIdx.x;
    const int w    = tid >> 5;
    const int l    = tid & 31;
    const int pair = w >> 1;
    const int net  = w & 1;          // 0 = mu, 1 = lv
    const int base_row = blockIdx.x * ROWS_PER_BLOCK + pair * RPW;

    float2 a0[RPW][4], a1[RPW][4], aout2[4];
    float2 xr2[4], lssum2[4];

#pragma unroll
    for (int e = 0; e < 4; e++) {
        float2 b0v = *(const float2*)&g_b0p[net][64 * e + 2 * l];
        float2 b1v = *(const float2*)&g_b1p[net][64 * e + 2 * l];
#pragma unroll
        for (int r = 0; r < RPW; r++) { a0[r][e] = b0v; a1[r][e] = b1v; }
    }
    {
        float b2v = g_b2[net][l];
#pragma unroll
        for (int rp = 0; rp < 4; rp++) aout2[rp] = make_float2(b2v, b2v);
    }
#pragma unroll
    for (int rp = 0; rp < 4; rp++) {
        lssum2[rp] = make_float2(0.f, 0.f);
        xr2[rp] = make_float2(x[(base_row + 2 * rp) * 32 + l],
                              x[(base_row + 2 * rp + 1) * 32 + l]);
    }

    // Prologue: prefetch step 1 into buffer 0.
    prefetch_step<9, 0>(0, 0, tid, 0, SW0, SW1, SW2);
    cp_commit();

    int buf = 0;
    for (int t = 1; t <= 32; ++t) {
        const int j = t - 1;
        const int tb = t & 1;
        // ---- emit exchange: lane j publishes its net's contribution ----
        if (l == j) {
            if (net == 0) {
#pragma unroll
                for (int rp = 0; rp < 4; rp++)
                    sD[tb][pair][rp] = make_float2(xr2[rp].x - aout2[rp].x,
                                                   xr2[rp].y - aout2[rp].y);
            } else {
#pragma unroll
                for (int rp = 0; rp < 4; rp++) {
                    float2 ls = make_float2(0.5f * aout2[rp].x, 0.5f * aout2[rp].y);
                    lssum2[rp].x += ls.x;
                    lssum2[rp].y += ls.y;
                    sI[tb][pair][rp] = make_float2(
                        __fdividef(1.f, __expf(ls.x) + EPSf),
                        __fdividef(1.f, __expf(ls.y) + EPSf));
                }
            }
        }

        cp_wait_all();
        __syncthreads();   // weights for step t ready + exchange visible

        // ---- everyone computes y for the 8 rows (broadcast LDS reads) ----
        const float* pD = (const float*)&sD[tb][pair][0];
        const float* pI = (const float*)&sI[tb][pair][0];
        float2 y2[RPW];
        {
            float4 d0 = ((const float4*)pD)[0], d1 = ((const float4*)pD)[1];
            float4 i0 = ((const float4*)pI)[0], i1 = ((const float4*)pI)[1];
            float yv[RPW] = {d0.x * i0.x, d0.y * i0.y, d0.z * i0.z, d0.w * i0.w,
                             d1.x * i1.x, d1.y * i1.y, d1.z * i1.z, d1.w * i1.w};
#pragma unroll
            for (int r = 0; r < RPW; r++) y2[r] = make_float2(yv[r], yv[r]);
        }
        // mu-warp lanes 0..7 store y for their row
        if (net == 0 && l < RPW)
            out[(base_row + l) * 32 + j] = pD[l] * pI[l];

        if (t == 32) break;

        if (t < 31) {
            const int tn = t + 1, jn = tn - 1;
            const int offn = (tn <= 9) ? 9 * (tn - 1) : 72 + 8 * (tn - 9);
            if (tn <= 8)       prefetch_step<9, 0>(jn, offn, tid, buf ^ 1, SW0, SW1, SW2);
            else if (tn <= 15) prefetch_step<8, 1>(jn, offn, tid, buf ^ 1, SW0, SW1, SW2);
            else if (tn <= 23) prefetch_step<8, 2>(jn, offn, tid, buf ^ 1, SW0, SW1, SW2);
            else               prefetch_step<8, 3>(jn, offn, tid, buf ^ 1, SW0, SW1, SW2);
            cp_commit();
        }

        const int off = (t <= 9) ? 9 * (t - 1) : 72 + 8 * (t - 9);
        if (t <= 8)
            do_step<9, 0>(l, off, buf, net, y2, a0, a1, aout2, SW0, SW1, SW2, sH0s[w], sH1s[w]);
        else if (t <= 15)
            do_step<8, 1>(l, off, buf, net, y2, a0, a1, aout2, SW0, SW1, SW2, sH0s[w], sH1s[w]);
        else if (t <= 23)
            do_step<8, 2>(l, off, buf, net, y2, a0, a1, aout2, SW0, SW1, SW2, sH0s[w], sH1s[w]);
        else
            do_step<8, 3>(l, off, buf, net, y2, a0, a1, aout2, SW0, SW1, SW2, sH0s[w], sH1s[w]);
        buf ^= 1;
    }

    // ---- logstd row-sums: lv-warp reduces lane-partial sums ----
    if (net == 1) {
#pragma unroll
        for (int rp = 0; rp < 4; rp++) {
            float sx = lssum2[rp].x, sy = lssum2[rp].y;
#pragma unroll
            for (int o = 16; o > 0; o >>= 1) {
                sx += __shfl_xor_sync(0xffffffffu, sx, o);
                sy += __shfl_xor_sync(0xffffffffu, sy, o);
            }
            if (l == 0) {
                out[Bb * Dd + base_row + 2 * rp]     = sx;
                out[Bb * Dd + base_row + 2 * rp + 1] = sy;
            }
        }
    }
}

extern "C" void kernel_launch(void* const* d_in, const int* in_sizes, int n_in,
                              void* d_out, int out_size)
{
    (void)in_sizes; (void)n_in; (void)out_size;
    const float* x = (const float*)d_in[0];

    prep_kernel<<<512, 256>>>(
        (const float*)d_in[1],  (const float*)d_in[2],  (const float*)d_in[3],
        (const float*)d_in[4],  (const float*)d_in[5],  (const float*)d_in[6],
        (const float*)d_in[7],  (const float*)d_in[8],  (const float*)d_in[9],
        (const float*)d_in[10], (const float*)d_in[11], (const float*)d_in[12]);

    const int dyn_smem = (1024 + 9216 + 1152) * 4;   // 45568 B
    cudaFuncSetAttribute(afmade_kernel,
                         cudaFuncAttributeMaxDynamicSharedMemorySize, dyn_smem);
    afmade_kernel<<<GRID, THREADS, dyn_smem>>>(x, (float*)d_out);
}